// round 4
// baseline (speedup 1.0000x reference)
#include <cuda_runtime.h>
#include <math.h>

#define T_LEN   2000000
#define NTAGS   5
#define START_T 3
#define STOP_T  4

#define CHUNK   56
#define GRID1   140
#define BLOCK1  256
#define LANES_TOT (GRID1 * BLOCK1)                       // 35840
#define LANES_ACT ((T_LEN - 1 + CHUNK - 1) / CHUNK)      // 35715
#define L_LAST    (LANES_ACT - 1)

__device__ float  g_P[LANES_TOT][9];
__device__ int    g_pb[LANES_TOT];
__device__ float  g_gold[LANES_TOT];
__device__ float  g_Mblk[GRID1][9];
__device__ int    g_Bblk[GRID1];
__device__ double g_Eb[GRID1][9];
__device__ int    g_EbB[GRID1];
__device__ float  g_A[LANES_TOT][3];
__device__ double g_part[LANES_TOT];
__device__ float  g_stop3[3];

__device__ __forceinline__ void renorm9(float* P, int& base) {
    float m = fmaxf(fmaxf(fmaxf(P[0], P[1]), fmaxf(P[2], P[3])),
                    fmaxf(fmaxf(P[4], P[5]), fmaxf(P[6], fmaxf(P[7], P[8]))));
    int e = (int)(__float_as_uint(m) >> 23) - 127;
    float sc = __uint_as_float((unsigned)(127 - e) << 23);
#pragma unroll
    for (int i = 0; i < 9; ++i) P[i] *= sc;
    base += e;
}

__device__ __forceinline__ void drenorm9(double* C, int& base) {
    double m = C[0];
#pragma unroll
    for (int i = 1; i < 9; ++i) m = fmax(m, C[i]);
    int e; frexp(m, &e);
    double sc = ldexp(1.0, -e);
#pragma unroll
    for (int i = 0; i < 9; ++i) C[i] *= sc;
    base += e;
}

// =============== K1: exact per-chunk 3x3 linear-semiring matrices + gold ===============
__global__ void __launch_bounds__(BLOCK1) crf_chunks(
        const float* __restrict__ feats, const int* __restrict__ tags,
        const float* __restrict__ trans) {
    __shared__ float sP[BLOCK1][9];
    __shared__ int   sB[BLOCK1];
    __shared__ float sTr[25];

    const float L2E = 1.4426950408889634f;
    int tid = threadIdx.x;
    if (tid < 25) sTr[tid] = trans[tid];

    float Tl[9];
#pragma unroll
    for (int i = 0; i < 3; ++i)
#pragma unroll
        for (int k = 0; k < 3; ++k)
            Tl[i * 3 + k] = exp2f(L2E * __ldg(&trans[i * NTAGS + k]));
    __syncthreads();

    int g     = blockIdx.x * BLOCK1 + tid;
    int start = 1 + g * CHUNK;
    int t1    = min(start + CHUNK, T_LEN);

    float P[9] = {1.f, 0.f, 0.f, 0.f, 1.f, 0.f, 0.f, 0.f, 1.f};
    int   base = 0;
    float gold = 0.f;

    if (start < T_LEN) {
        int prev = __ldg(&tags[start - 1]);
        int cnt = 0;
        for (int t = start; t < t1; ++t) {
            float f0 = __ldg(&feats[t * 5 + 0]);
            float f1 = __ldg(&feats[t * 5 + 1]);
            float f2 = __ldg(&feats[t * 5 + 2]);
            int cur = __ldg(&tags[t]);
            float e0 = exp2f(L2E * f0), e1 = exp2f(L2E * f1), e2 = exp2f(L2E * f2);
            float a0 = e0 * Tl[0], a1 = e0 * Tl[1], a2 = e0 * Tl[2];
            float b0 = e1 * Tl[3], b1 = e1 * Tl[4], b2 = e1 * Tl[5];
            float d0 = e2 * Tl[6], d1 = e2 * Tl[7], d2 = e2 * Tl[8];
            float q0 = a0 * P[0] + a1 * P[3] + a2 * P[6];
            float q1 = a0 * P[1] + a1 * P[4] + a2 * P[7];
            float q2 = a0 * P[2] + a1 * P[5] + a2 * P[8];
            float q3 = b0 * P[0] + b1 * P[3] + b2 * P[6];
            float q4 = b0 * P[1] + b1 * P[4] + b2 * P[7];
            float q5 = b0 * P[2] + b1 * P[5] + b2 * P[8];
            float q6 = d0 * P[0] + d1 * P[3] + d2 * P[6];
            float q7 = d0 * P[1] + d1 * P[4] + d2 * P[7];
            float q8 = d0 * P[2] + d1 * P[5] + d2 * P[8];
            P[0]=q0; P[1]=q1; P[2]=q2; P[3]=q3; P[4]=q4; P[5]=q5; P[6]=q6; P[7]=q7; P[8]=q8;
            float emit = (cur == 0) ? f0 : ((cur == 1) ? f1 : f2);
            gold += emit + sTr[cur * NTAGS + prev];
            prev = cur;
            if (((++cnt) & 3) == 0) renorm9(P, base);
        }
        renorm9(P, base);
    }

#pragma unroll
    for (int i = 0; i < 9; ++i) g_P[g][i] = P[i];
    g_pb[g]   = base;
    g_gold[g] = gold;

    // ordered in-block tree (later matrix left-multiplies earlier) -> block total
#pragma unroll
    for (int i = 0; i < 9; ++i) sP[tid][i] = P[i];
    sB[tid] = base;
    __syncthreads();
    for (int s = 1; s < BLOCK1; s <<= 1) {
        float A[9], Bm[9], C[9]; int nb = 0; bool act = ((tid & (2*s-1)) == 0);
        if (act) {
#pragma unroll
            for (int i = 0; i < 9; ++i) { A[i] = sP[tid][i]; Bm[i] = sP[tid + s][i]; }
            nb = sB[tid] + sB[tid + s];
#pragma unroll
            for (int i = 0; i < 3; ++i)
#pragma unroll
                for (int j = 0; j < 3; ++j)
                    C[i*3+j] = Bm[i*3+0]*A[0+j] + Bm[i*3+1]*A[3+j] + Bm[i*3+2]*A[6+j];
            renorm9(C, nb);
        }
        __syncthreads();
        if (act) {
#pragma unroll
            for (int i = 0; i < 9; ++i) sP[tid][i] = C[i];
            sB[tid] = nb;
        }
        __syncthreads();
    }
    if (tid == 0) {
#pragma unroll
        for (int i = 0; i < 9; ++i) g_Mblk[blockIdx.x][i] = sP[0][i];
        g_Bblk[blockIdx.x] = sB[0];
    }
}

// =============== K2: exclusive prefix over 140 block totals (double) ===============
__global__ void __launch_bounds__(BLOCK1) crf_blockscan() {
    __shared__ double sM[BLOCK1][9];
    __shared__ int    sb[BLOCK1];
    int tid = threadIdx.x;
    if (tid < GRID1) {
#pragma unroll
        for (int i = 0; i < 9; ++i) sM[tid][i] = (double)g_Mblk[tid][i];
        sb[tid] = g_Bblk[tid];
    } else {
#pragma unroll
        for (int i = 0; i < 9; ++i) sM[tid][i] = (i % 4 == 0) ? 1.0 : 0.0;
        sb[tid] = 0;
    }
    __syncthreads();
    // ordered Hillis-Steele inclusive scan
    for (int s = 1; s < BLOCK1; s <<= 1) {
        double A[9], Bm[9], C[9]; int nb = 0; bool act = (tid >= s);
        if (act) {
#pragma unroll
            for (int i = 0; i < 9; ++i) { Bm[i] = sM[tid][i]; A[i] = sM[tid - s][i]; }
            nb = sb[tid] + sb[tid - s];
#pragma unroll
            for (int i = 0; i < 3; ++i)
#pragma unroll
                for (int j = 0; j < 3; ++j)
                    C[i*3+j] = Bm[i*3+0]*A[0+j] + Bm[i*3+1]*A[3+j] + Bm[i*3+2]*A[6+j];
            drenorm9(C, nb);
        }
        __syncthreads();
        if (act) {
#pragma unroll
            for (int i = 0; i < 9; ++i) sM[tid][i] = C[i];
            sb[tid] = nb;
        }
        __syncthreads();
    }
    if (tid < GRID1) {
        if (tid == 0) {
#pragma unroll
            for (int i = 0; i < 9; ++i) g_Eb[0][i] = (i % 4 == 0) ? 1.0 : 0.0;
            g_EbB[0] = 0;
        } else {
#pragma unroll
            for (int i = 0; i < 9; ++i) g_Eb[tid][i] = sM[tid - 1][i];
            g_EbB[tid] = sb[tid - 1];
        }
    }
}

// =============== K3a: per-lane boundary vectors A_k (absolute log-domain) ===============
__global__ void __launch_bounds__(BLOCK1) crf_prefix(
        const float* __restrict__ feats, const float* __restrict__ trans) {
    __shared__ float sP[BLOCK1][9];
    __shared__ int   sB[BLOCK1];
    int tid = threadIdx.x;
    int g   = blockIdx.x * BLOCK1 + tid;

#pragma unroll
    for (int i = 0; i < 9; ++i) sP[tid][i] = g_P[g][i];
    sB[tid] = g_pb[g];
    __syncthreads();

    // ordered inclusive scan of lane matrices within the block (fp32 + base)
    for (int s = 1; s < BLOCK1; s <<= 1) {
        float A[9], Bm[9], C[9]; int nb = 0; bool act = (tid >= s);
        if (act) {
#pragma unroll
            for (int i = 0; i < 9; ++i) { Bm[i] = sP[tid][i]; A[i] = sP[tid - s][i]; }
            nb = sB[tid] + sB[tid - s];
#pragma unroll
            for (int i = 0; i < 3; ++i)
#pragma unroll
                for (int j = 0; j < 3; ++j)
                    C[i*3+j] = Bm[i*3+0]*A[0+j] + Bm[i*3+1]*A[3+j] + Bm[i*3+2]*A[6+j];
            renorm9(C, nb);
        }
        __syncthreads();
        if (act) {
#pragma unroll
            for (int i = 0; i < 9; ++i) sP[tid][i] = C[i];
            sB[tid] = nb;
        }
        __syncthreads();
    }

    // exclusive local prefix for this lane
    double exL[9]; int bL;
    if (tid == 0) {
#pragma unroll
        for (int i = 0; i < 9; ++i) exL[i] = (i % 4 == 0) ? 1.0 : 0.0;
        bL = 0;
    } else {
#pragma unroll
        for (int i = 0; i < 9; ++i) exL[i] = (double)sP[tid - 1][i];
        bL = sB[tid - 1];
    }

    double Eb[9]; int bE = g_EbB[blockIdx.x];
#pragma unroll
    for (int i = 0; i < 9; ++i) Eb[i] = g_Eb[blockIdx.x][i];

    // global exclusive prefix = exL (later) * Eb (earlier)
    double Cd[9]; int base = bL + bE;
#pragma unroll
    for (int i = 0; i < 3; ++i)
#pragma unroll
        for (int j = 0; j < 3; ++j)
            Cd[i*3+j] = exL[i*3+0]*Eb[0+j] + exL[i*3+1]*Eb[3+j] + exL[i*3+2]*Eb[6+j];

    // v0 (double, literal 5-state step 0), components 0..2
    double v0[3];
    for (int i = 0; i < 3; ++i) {
        double a[5]; double m = -1e300;
        for (int j = 0; j < 5; ++j) {
            a[j] = (double)trans[i * NTAGS + j] + ((j == START_T) ? 0.0 : -10000.0);
            if (a[j] > m) m = a[j];
        }
        double ss = 0.0;
        for (int j = 0; j < 5; ++j) ss += exp(a[j] - m);
        v0[i] = m + log(ss) + (double)feats[i];
    }
    double c0 = fmax(fmax(v0[0], v0[1]), v0[2]);
    double u0[3];
    for (int j = 0; j < 3; ++j) u0[j] = exp(v0[j] - c0);

    for (int i = 0; i < 3; ++i) {
        double w = Cd[i*3+0]*u0[0] + Cd[i*3+1]*u0[1] + Cd[i*3+2]*u0[2];
        g_A[g][i] = (float)(log(w) + (double)base * 0.6931471805599453 + c0);
    }
}

// =============== K3b: fp32 absolute-scale quantized emulation per chunk ===============
__global__ void __launch_bounds__(BLOCK1) crf_emulate(
        const float* __restrict__ feats, const float* __restrict__ trans) {
    __shared__ float sTr[25];
    int tid = threadIdx.x;
    if (tid < 25) sTr[tid] = trans[tid];
    __syncthreads();

    int g = blockIdx.x * BLOCK1 + tid;
    if (g >= LANES_ACT) { g_part[g] = 0.0; return; }

    float fv0 = g_A[g][0], fv1 = g_A[g][1], fv2 = g_A[g][2];
    int start = 1 + g * CHUNK;
    int t1    = min(start + CHUNK, T_LEN);

    float t00=sTr[0],  t01=sTr[1],  t02=sTr[2];
    float t10=sTr[5],  t11=sTr[6],  t12=sTr[7];
    float t20=sTr[10], t21=sTr[11], t22=sTr[12];

    for (int t = start; t < t1; ++t) {
        float f0 = __ldg(&feats[t * 5 + 0]);
        float f1 = __ldg(&feats[t * 5 + 1]);
        float f2 = __ldg(&feats[t * 5 + 2]);
        // a_ij = round_fp32(fv_j + trans[i,j]) at absolute magnitude (the bias source)
        float a00=__fadd_rn(fv0,t00), a01=__fadd_rn(fv1,t01), a02=__fadd_rn(fv2,t02);
        float a10=__fadd_rn(fv0,t10), a11=__fadd_rn(fv1,t11), a12=__fadd_rn(fv2,t12);
        float a20=__fadd_rn(fv0,t20), a21=__fadd_rn(fv1,t21), a22=__fadd_rn(fv2,t22);
        float m0=fmaxf(fmaxf(a00,a01),a02);
        float m1=fmaxf(fmaxf(a10,a11),a12);
        float m2=fmaxf(fmaxf(a20,a21),a22);
        float s0=__expf(a00-m0)+__expf(a01-m0)+__expf(a02-m0);
        float s1=__expf(a10-m1)+__expf(a11-m1)+__expf(a12-m1);
        float s2=__expf(a20-m2)+__expf(a21-m2)+__expf(a22-m2);
        fv0=__fadd_rn(__fadd_rn(__logf(s0),m0),f0);
        fv1=__fadd_rn(__fadd_rn(__logf(s1),m1),f1);
        fv2=__fadd_rn(__fadd_rn(__logf(s2),m2),f2);
    }

    if (g < L_LAST) {
        double p = ((double)fv0 - (double)g_A[g+1][0])
                 + ((double)fv1 - (double)g_A[g+1][1])
                 + ((double)fv2 - (double)g_A[g+1][2]);
        g_part[g] = p / 3.0;
    } else {   // g == L_LAST
        g_stop3[0] = __fadd_rn(fv0, sTr[STOP_T * NTAGS + 0]);
        g_stop3[1] = __fadd_rn(fv1, sTr[STOP_T * NTAGS + 1]);
        g_stop3[2] = __fadd_rn(fv2, sTr[STOP_T * NTAGS + 2]);
        g_part[g] = 0.0;
    }
}

// =============== K4: deterministic reductions + epilogue ===============
__global__ void __launch_bounds__(BLOCK1) crf_out(
        const float* __restrict__ feats, const int* __restrict__ tags,
        const float* __restrict__ trans, float* __restrict__ out) {
    __shared__ double red[BLOCK1];
    int tid = threadIdx.x;

    double s = 0.0;
    for (int i = tid; i < LANES_TOT; i += BLOCK1) s += g_part[i];
    red[tid] = s; __syncthreads();
    for (int k = BLOCK1 / 2; k > 0; k >>= 1) {
        if (tid < k) red[tid] += red[tid + k];
        __syncthreads();
    }
    double mu = red[0]; __syncthreads();

    double sg = 0.0;
    for (int i = tid; i < LANES_TOT; i += BLOCK1) sg += (double)g_gold[i];
    red[tid] = sg; __syncthreads();
    for (int k = BLOCK1 / 2; k > 0; k >>= 1) {
        if (tid < k) red[tid] += red[tid + k];
        __syncthreads();
    }
    double goldsum = red[0];

    if (tid == 0) {
        double b0 = (double)g_stop3[0], b1 = (double)g_stop3[1], b2 = (double)g_stop3[2];
        double m = fmax(fmax(b0, b1), b2);
        double alpha = m + log(exp(b0 - m) + exp(b1 - m) + exp(b2 - m)) + mu;

        int tg0 = tags[0];
        int tgL = tags[T_LEN - 1];
        double gold = goldsum
                    + (double)trans[tg0 * NTAGS + START_T]
                    + (double)feats[tg0]
                    + (double)trans[STOP_T * NTAGS + tgL];
        out[0] = (float)(alpha - gold);
    }
}

extern "C" void kernel_launch(void* const* d_in, const int* in_sizes, int n_in,
                              void* d_out, int out_size) {
    const float* feats = nullptr;
    const int*   tags  = nullptr;
    const float* trans = nullptr;
    for (int i = 0; i < n_in; ++i) {
        if (in_sizes[i] == NTAGS * NTAGS)      trans = (const float*)d_in[i];
        else if (in_sizes[i] == T_LEN)         tags  = (const int*)d_in[i];
        else                                   feats = (const float*)d_in[i];
    }
    float* out = (float*)d_out;

    crf_chunks<<<GRID1, BLOCK1>>>(feats, tags, trans);
    crf_blockscan<<<1, BLOCK1>>>();
    crf_prefix<<<GRID1, BLOCK1>>>(feats, trans);
    crf_emulate<<<GRID1, BLOCK1>>>(feats, trans);
    crf_out<<<1, BLOCK1>>>(feats, tags, trans, out);
}